// round 16
// baseline (speedup 1.0000x reference)
#include <cuda_runtime.h>
#include <cuda_bf16.h>

#define R_     512
#define C_     256
#define H_     200
#define W_     200
#define OUTK   7
#define HW_    (H_*W_)
#define CHUNK  32   // channels per block; warp g owns {g, g+8, g+16, g+24}
#define OSZ    (OUTK * OUTK)
#define ROWMAX 28   // max union row span (<= 26)

// ---------------------------------------------------------------------------
// Fused-oy RoIAlign, register accumulators (R10 structure, registers fixed).
// Grid (512 roi, 8 chunk), chunk slowest -> per-phase set ~17 MB L2-resident.
//
// One flat loop over the union row span (~13.4 rows/ch, the unique-row
// minimum). Reduction into 7 oy bins runs ENTIRELY on the FMA pipe via
// packed fma.rn.f32x2 into 16 u64 accumulators (4ch x 4 oy-pairs); the only
// MIO ops per row are 4 LDG + 2 LDS.128. Shfl x-reduce happens once in the
// epilogue (56/warp), not per row (the R15 lesson: per-row shfl cancels the
// LDG savings in the same MIO budget).
//
// Register fixes vs R10 (72 regs, occ 34%):
//  - weight pairs come free: LDS.128 -> float4 -> u64 views of .xy/.zw
//  - xw factored out of the loop (applied once in the epilogue)
//  - one base pointer, channel strides as compile-time LDG offsets
//  - __launch_bounds__(256, 4) caps regs at 64 (occ >= 50%)
// Staged SMEM writeout (R14) for coalesced stores.
// ---------------------------------------------------------------------------

__device__ __forceinline__ unsigned long long pack2(float lo, float hi) {
    unsigned long long d;
    asm("mov.b64 %0, {%1, %2};" : "=l"(d) : "f"(lo), "f"(hi));
    return d;
}
__device__ __forceinline__ void fma2(unsigned long long& d,
                                     unsigned long long a,
                                     unsigned long long b) {
    asm("fma.rn.f32x2 %0, %1, %2, %0;" : "+l"(d) : "l"(a), "l"(b));
}
__device__ __forceinline__ float lo2(unsigned long long v) {
    float a, b; asm("mov.b64 {%0, %1}, %2;" : "=f"(a), "=f"(b) : "l"(v)); return a;
}
__device__ __forceinline__ float hi2(unsigned long long v) {
    float a, b; asm("mov.b64 {%0, %1}, %2;" : "=f"(a), "=f"(b) : "l"(v)); return b;
}

__global__ __launch_bounds__(256, 4) void roialign_kernel(
    const float* __restrict__ feat, const float* __restrict__ rois,
    float* __restrict__ out)
{
    int r   = blockIdx.x;
    int ch0 = blockIdx.y * CHUNK;

    __shared__ __align__(16) float s_wt[ROWMAX * 8];  // [row][oy(7)+pad0]
    __shared__ int   s_xi[28];
    __shared__ float s_xw[28];
    __shared__ int   s_yidx[28];
    __shared__ float s_ywt[28];
    __shared__ int   s_rmin, s_rcnt, s_boff;
    __shared__ float s_out[CHUNK * OSZ];

    int tid  = threadIdx.x;
    int lane = tid & 31;
    int warp = tid >> 5;

    if (warp < 2) {                  // warp0: x-taps, warp1: y-taps + range
        const float* ro = rois + r * 5;
        bool isx = (warp == 0);
        float p1 = (isx ? ro[1] : ro[2]) * 0.25f;
        float p2 = (isx ? ro[3] : ro[4]) * 0.25f;
        float bin = fmaxf(p2 - p1, 1.0f) * (1.0f / (float)OUTK);

        int t   = min(lane, 27);
        int o   = t >> 2;
        int s   = (t >> 1) & 1;
        int tap = t & 1;
        float y = p1 + ((float)o + ((float)s + 0.5f) * 0.5f) * bin;
        bool valid = (y >= -1.0f) && (y <= 200.0f);
        float yc = fminf(fmaxf(y, 0.0f), 199.0f);
        int   yl = (int)floorf(yc);
        int   yh = min(yl + 1, 199);
        float fl = yc - (float)yl;
        float wv = tap ? fl : (1.0f - fl);
        if (!valid) wv = 0.0f;
        int   iv = tap ? yh : yl;

        if (lane < 28) {
            if (isx) { s_xi[lane] = iv;   s_xw[lane] = wv; }
            else     { s_yidx[lane] = iv; s_ywt[lane] = wv; }
        }
        if (!isx) {
            int vmin = (lane < 28) ? iv : 10000;
            int vmax = (lane < 28) ? iv : -1;
            #pragma unroll
            for (int d = 16; d; d >>= 1) {
                vmin = min(vmin, __shfl_xor_sync(0xffffffffu, vmin, d));
                vmax = max(vmax, __shfl_xor_sync(0xffffffffu, vmax, d));
            }
            if (lane == 0) { s_rmin = vmin; s_rcnt = vmax - vmin + 1; }
        }
        if (tid == 0) s_boff = (int)ro[0] * (C_ * HW_);
    }
    __syncthreads();

    // Dense per-row y-weight table (col 7 stays 0 as FFMA2 pad).
    if (tid < ROWMAX * 8) {
        int row = tid >> 3;
        int oy  = tid & 7;
        float w = 0.f;
        if (oy < 7) {
            int tgt = s_rmin + row;
            #pragma unroll
            for (int k = 0; k < 4; k++) {
                int   i = s_yidx[oy * 4 + k];
                float v = s_ywt[oy * 4 + k];
                w += (i == tgt) ? v : 0.f;
            }
        }
        s_wt[tid] = w;
    }
    __syncthreads();

    int l    = min(lane, 27);
    int   xi = s_xi[l];
    float xw = s_xw[l] * 0.25f;      // applied once in the epilogue
    int rmin = s_rmin;
    int rcnt = s_rcnt;

    const float* fb = feat + s_boff + (size_t)(ch0 + warp) * HW_;

    unsigned long long acc[4][4];    // [channel][oy-pair]
    #pragma unroll
    for (int c = 0; c < 4; c++)
        #pragma unroll
        for (int p = 0; p < 4; p++) acc[c][p] = 0ull;

    int base = rmin * W_ + xi;

    #pragma unroll 2
    for (int j = 0; j < rcnt; j++, base += W_) {
        float v0 = __ldg(fb + base);
        float v1 = __ldg(fb + base +  8 * HW_);
        float v2 = __ldg(fb + base + 16 * HW_);
        float v3 = __ldg(fb + base + 24 * HW_);
        // weight pairs straight from LDS.128 register quads (no packs)
        float4 wlo = *(const float4*)&s_wt[j * 8];
        float4 whi = *(const float4*)&s_wt[j * 8 + 4];
        unsigned long long w01 = *(const unsigned long long*)&wlo.x;
        unsigned long long w23 = *(const unsigned long long*)&wlo.z;
        unsigned long long w45 = *(const unsigned long long*)&whi.x;
        unsigned long long w6z = *(const unsigned long long*)&whi.z;
        unsigned long long vv0 = pack2(v0, v0);
        unsigned long long vv1 = pack2(v1, v1);
        unsigned long long vv2 = pack2(v2, v2);
        unsigned long long vv3 = pack2(v3, v3);
        fma2(acc[0][0], vv0, w01); fma2(acc[0][1], vv0, w23);
        fma2(acc[0][2], vv0, w45); fma2(acc[0][3], vv0, w6z);
        fma2(acc[1][0], vv1, w01); fma2(acc[1][1], vv1, w23);
        fma2(acc[1][2], vv1, w45); fma2(acc[1][3], vv1, w6z);
        fma2(acc[2][0], vv2, w01); fma2(acc[2][1], vv2, w23);
        fma2(acc[2][2], vv2, w45); fma2(acc[2][3], vv2, w6z);
        fma2(acc[3][0], vv3, w01); fma2(acc[3][1], vv3, w23);
        fma2(acc[3][2], vv3, w45); fma2(acc[3][3], vv3, w6z);
    }

    // Epilogue: x-weight, end-only 4-lane shfl reduce, stage to SMEM.
    int  ox      = l >> 2;
    bool doStore = (lane < 28) && ((lane & 3) == 0);

    #pragma unroll
    for (int c = 0; c < 4; c++) {
        float vals[7] = { lo2(acc[c][0]), hi2(acc[c][0]),
                          lo2(acc[c][1]), hi2(acc[c][1]),
                          lo2(acc[c][2]), hi2(acc[c][2]),
                          lo2(acc[c][3]) };
        float* srow = &s_out[(warp + c * 8) * OSZ + ox];
        #pragma unroll
        for (int oy = 0; oy < 7; oy++) {
            float v = vals[oy] * xw;
            v += __shfl_xor_sync(0xffffffffu, v, 1);
            v += __shfl_xor_sync(0xffffffffu, v, 2);
            if (doStore) srow[oy * OUTK] = v;
        }
    }
    __syncthreads();

    // Coalesced writeout of the contiguous per-(roi, chunk) region.
    float* ob = out + ((size_t)r * C_ + ch0) * OSZ;
    #pragma unroll
    for (int i = 0; i < (CHUNK * OSZ + 255) / 256; i++) {
        int idx = tid + i * 256;
        if (idx < CHUNK * OSZ)
            ob[idx] = s_out[idx];
    }
}

extern "C" void kernel_launch(void* const* d_in, const int* in_sizes, int n_in,
                              void* d_out, int out_size) {
    const float* feat = (const float*)d_in[0];
    const float* rois = (const float*)d_in[1];
    if (n_in >= 2 && in_sizes[0] == R_ * 5) {  // defensive against input order
        feat = (const float*)d_in[1];
        rois = (const float*)d_in[0];
    }
    float* out = (float*)d_out;

    dim3 grid(R_, C_ / CHUNK);       // chunk slowest -> L2 phase blocking
    roialign_kernel<<<grid, 256>>>(feat, rois, out);
}

// round 17
// speedup vs baseline: 1.1272x; 1.1272x over previous
#include <cuda_runtime.h>
#include <cuda_bf16.h>

#define R_      512
#define C_      256
#define H_      200
#define W_      200
#define OUTK    7
#define HW_     (H_*W_)
#define CHUNK   32   // channels per block; warp g owns {g, g+8, g+16, g+24}
#define OSZ     (OUTK * OUTK)
#define PROWS   12   // max rows per oy-pair span (<= ~9 in practice)

// ---------------------------------------------------------------------------
// Pairwise-oy-fused RoIAlign. Grid (512 roi, 8 chunk), chunk slowest ->
// per-phase feature set (~17 MB) L2-resident (DRAM ~157 MB compulsory).
//
// oy bins processed in pairs {0,1},{2,3},{4,5},{6}: adjacent bins share
// ~1.5 rows, so the pair's union span (~4.3 rows) is loaded once instead of
// twice -> 20.3 -> ~15.8 row-loads per channel (-22% LDG wavefronts), while
// needing only 2 accumulators per channel (8 floats/thread, regs ~36,
// occupancy preserved -- the fused-7-oy versions died at 47-34% occ).
//
// Per row: 4 LDG + 1 LDS.64 (dense weight pair for this row), FMA-pipe
// accumulation only -- no per-row shfl (R15 lesson). Epilogue: 4-lane shfl
// reduce per (pair, channel), stage to s_out, coalesced block writeout (R14).
// ---------------------------------------------------------------------------

__global__ __launch_bounds__(256) void roialign_kernel(
    const float* __restrict__ feat, const float* __restrict__ rois,
    float* __restrict__ out)
{
    int r   = blockIdx.x;
    int ch0 = blockIdx.y * CHUNK;

    __shared__ __align__(8) float2 s_pw[4 * PROWS];  // [pair][row] -> (wA,wB)
    __shared__ int   s_xi[28];
    __shared__ float s_xw[28];
    __shared__ int   s_yidx[28];
    __shared__ float s_ywt[28];
    __shared__ int   s_prb[4], s_prc[4];             // per-pair row base/count
    __shared__ int   s_boff;
    __shared__ float s_out[CHUNK * OSZ];

    int tid  = threadIdx.x;
    int lane = tid & 31;
    int warp = tid >> 5;

    if (warp < 2) {                  // warp0: x-taps, warp1: y-taps
        const float* ro = rois + r * 5;
        bool isx = (warp == 0);
        float p1 = (isx ? ro[1] : ro[2]) * 0.25f;
        float p2 = (isx ? ro[3] : ro[4]) * 0.25f;
        float bin = fmaxf(p2 - p1, 1.0f) * (1.0f / (float)OUTK);

        int t   = min(lane, 27);
        int o   = t >> 2;
        int s   = (t >> 1) & 1;
        int tap = t & 1;
        float y = p1 + ((float)o + ((float)s + 0.5f) * 0.5f) * bin;
        bool valid = (y >= -1.0f) && (y <= 200.0f);
        float yc = fminf(fmaxf(y, 0.0f), 199.0f);
        int   yl = (int)floorf(yc);
        int   yh = min(yl + 1, 199);
        float fl = yc - (float)yl;
        float wv = tap ? fl : (1.0f - fl);
        if (!valid) wv = 0.0f;
        int   iv = tap ? yh : yl;

        if (lane < 28) {
            if (isx) { s_xi[lane] = iv;   s_xw[lane] = wv; }
            else     { s_yidx[lane] = iv; s_ywt[lane] = wv; }
        }
        if (tid == 0) s_boff = (int)ro[0] * (C_ * HW_);
    }
    __syncthreads();

    // Per-pair row ranges. Taps sorted within/across bins:
    // rb = first tap of the pair's first bin, re = last tap of its last bin.
    if (tid < 4) {
        int rb = s_yidx[tid * 8];
        int re = (tid < 3) ? s_yidx[tid * 8 + 7] : s_yidx[27];
        s_prb[tid] = rb;
        s_prc[tid] = re - rb + 1;    // <= ~9 < PROWS
    }
    // Dense weight pairs: (pair, row) -> (w for oy=2p, w for oy=2p+1).
    if (tid >= 64 && tid < 64 + 4 * PROWS) {
        int t2   = tid - 64;
        int pair = t2 / PROWS;
        int row  = t2 - pair * PROWS;
        int oyA  = pair * 2;
        int rb   = s_yidx[oyA * 4];
        int tgt  = rb + row;
        float wA = 0.f, wB = 0.f;
        #pragma unroll
        for (int k = 0; k < 4; k++) {
            wA += (s_yidx[oyA * 4 + k] == tgt) ? s_ywt[oyA * 4 + k] : 0.f;
            if (pair < 3)
                wB += (s_yidx[(oyA + 1) * 4 + k] == tgt) ? s_ywt[(oyA + 1) * 4 + k] : 0.f;
        }
        s_pw[t2] = make_float2(wA, wB);
    }
    __syncthreads();

    int l    = min(lane, 27);
    int   xi = s_xi[l];
    float xw = s_xw[l] * 0.25f;      // fold S*S mean
    const float* fb = feat + s_boff + (size_t)(ch0 + warp) * HW_;

    int  ox      = l >> 2;
    bool doStore = (lane < 28) && ((lane & 3) == 0);

    #pragma unroll
    for (int pair = 0; pair < 4; pair++) {
        int rb = s_prb[pair];
        int rc = s_prc[pair];
        const float2* pw = &s_pw[pair * PROWS];

        float aE0 = 0.f, aE1 = 0.f, aE2 = 0.f, aE3 = 0.f;  // oy = 2p
        float aO0 = 0.f, aO1 = 0.f, aO2 = 0.f, aO3 = 0.f;  // oy = 2p+1
        int base = rb * W_ + xi;

        #pragma unroll 2
        for (int j = 0; j < rc; j++, base += W_) {
            float v0 = __ldg(fb + base);
            float v1 = __ldg(fb + base +  8 * HW_);
            float v2 = __ldg(fb + base + 16 * HW_);
            float v3 = __ldg(fb + base + 24 * HW_);
            float2 w = pw[j];
            aE0 += w.x * v0;  aO0 += w.y * v0;
            aE1 += w.x * v1;  aO1 += w.y * v1;
            aE2 += w.x * v2;  aO2 += w.y * v2;
            aE3 += w.x * v3;  aO3 += w.y * v3;
        }

        float vE[4] = { aE0, aE1, aE2, aE3 };
        float vO[4] = { aO0, aO1, aO2, aO3 };
        #pragma unroll
        for (int c = 0; c < 4; c++) {
            float e = vE[c] * xw;
            e += __shfl_xor_sync(0xffffffffu, e, 1);
            e += __shfl_xor_sync(0xffffffffu, e, 2);
            if (doStore)
                s_out[(warp + c * 8) * OSZ + (pair * 2) * OUTK + ox] = e;
            if (pair < 3) {
                float o2 = vO[c] * xw;
                o2 += __shfl_xor_sync(0xffffffffu, o2, 1);
                o2 += __shfl_xor_sync(0xffffffffu, o2, 2);
                if (doStore)
                    s_out[(warp + c * 8) * OSZ + (pair * 2 + 1) * OUTK + ox] = o2;
            }
        }
    }
    __syncthreads();

    // Coalesced writeout of the contiguous per-(roi, chunk) region.
    float* ob = out + ((size_t)r * C_ + ch0) * OSZ;
    #pragma unroll
    for (int i = 0; i < (CHUNK * OSZ + 255) / 256; i++) {
        int idx = tid + i * 256;
        if (idx < CHUNK * OSZ)
            ob[idx] = s_out[idx];
    }
}

extern "C" void kernel_launch(void* const* d_in, const int* in_sizes, int n_in,
                              void* d_out, int out_size) {
    const float* feat = (const float*)d_in[0];
    const float* rois = (const float*)d_in[1];
    if (n_in >= 2 && in_sizes[0] == R_ * 5) {  // defensive against input order
        feat = (const float*)d_in[1];
        rois = (const float*)d_in[0];
    }
    float* out = (float*)d_out;

    dim3 grid(R_, C_ / CHUNK);       // chunk slowest -> L2 phase blocking
    roialign_kernel<<<grid, 256>>>(feat, rois, out);
}